// round 15
// baseline (speedup 1.0000x reference)
#include <cuda_runtime.h>
#include <cstdint>

// ---------------------------------------------------------------------------
// GungnirHalfKA (NNUE) batched eval, GB300 sm_103a — Round 13
// Single fused launch: table-convert blocks + nnue blocks with per-row
// readiness flags, so the LTS-bound gather overlaps the DRAM-bound convert.
// ---------------------------------------------------------------------------

#define FT_IN   45056
#define FT_OUT  1024
#define NB_MAX  8

__device__ signed char g_ftq[(size_t)FT_IN * FT_OUT];   // 46 MB, int8-exact
__device__ signed char g_fc0q[NB_MAX * 16 * FT_OUT];    // 128 KB, int8-exact
__device__ signed char g_fc1q[NB_MAX * 32 * 32];        // 8 KB, int8-exact
__device__ unsigned    g_bq[FT_OUT / 2];                // ft bias, 2x i16 packed

struct SyncT {
    int rowflag[FT_IN];   // 1 = row converted
    int psq_part[16];     // bit1 = done, bit0 = nonzero
    int aux_done;         // counts aux blocks (fc0/fc1/bias)
    int ft_done;          // counts ft-convert blocks
};
__device__ SyncT g_sync;

// ---- grid layout ----------------------------------------------------------
#define SCAN_BLOCKS 16
#define AUX_BLOCKS  137                        /* 128 fc0 + 8 fc1 + 1 bias */
#define FT_CVT_BLOCKS (FT_IN / 4)              /* 11264, 4 rows each */
#define NN0 (SCAN_BLOCKS + AUX_BLOCKS + FT_CVT_BLOCKS)   /* 11417 */
#define PSQ_F4      (FT_IN * 8 / 4)            /* 90112 */
#define PSQ_PER_BLK (PSQ_F4 / SCAN_BLOCKS)     /* 5632  */

__device__ __forceinline__ float q8f(float x) {
    return fminf(fmaxf(rintf(x), -128.f), 127.f);
}
__device__ __forceinline__ float q16f(float x) {
    return fminf(fmaxf(rintf(x), -32768.f), 32767.f);
}
__device__ __forceinline__ float q32f(float x) {
    return fminf(fmaxf(rintf(x), -2147483648.f), 2147483647.f);
}
__device__ __forceinline__ float clip127(float x) {
    return fminf(fmaxf(x, 0.f), 127.f);
}
__device__ __forceinline__ char4 q8x4(const float4& v) {
    char4 c;
    c.x = (signed char)q8f(v.x);
    c.y = (signed char)q8f(v.y);
    c.z = (signed char)q8f(v.z);
    c.w = (signed char)q8f(v.w);
    return c;
}

// Widen 4 packed int8 -> 2x(2x int16) and accumulate.
__device__ __forceinline__ void acc4(unsigned* a, unsigned v) {
    unsigned lo, hi;
    asm("prmt.b32 %0, %1, 0, 0x9180;" : "=r"(lo) : "r"(v));
    asm("prmt.b32 %0, %1, 0, 0xB3A2;" : "=r"(hi) : "r"(v));
    a[0] = __vadd2(a[0], lo);
    a[1] = __vadd2(a[1], hi);
}
__device__ __forceinline__ void acc16(unsigned* acc, const int4& v) {
    acc4(acc + 0, (unsigned)v.x);
    acc4(acc + 2, (unsigned)v.y);
    acc4(acc + 4, (unsigned)v.z);
    acc4(acc + 6, (unsigned)v.w);
}

__device__ __forceinline__ void mulbytes(unsigned a, unsigned c,
                                         int& lo, int& hi) {
    lo = (int)(((a & 0xFFu) * (c & 0xFFu)) |
               ((((a >> 8) & 0xFFu) * ((c >> 8) & 0xFFu)) << 16));
    hi = (int)((((a >> 16) & 0xFFu) * ((c >> 16) & 0xFFu)) |
               (((a >> 24) * (c >> 24)) << 16));
}
__device__ __forceinline__ float sb2f(unsigned w, int j) {
    return (float)((int)(w << (24 - 8 * j)) >> 24);
}
__device__ __forceinline__ int vflag(int r) {
    return *((volatile int*)&g_sync.rowflag[r]);
}

// Gather one side; POLL=true waits on per-row flags (rows arriving from the
// converter blocks). Integer accumulation -> identical result either path.
template <bool POLL>
__device__ __forceinline__ void gather_side(const int* feats, int n, int d0,
                                            unsigned* acc) {
    int f = 0;
    for (; f + 8 <= n; f += 8) {
        int4 ix0 = *reinterpret_cast<const int4*>(feats + f);
        int4 ix1 = *reinterpret_cast<const int4*>(feats + f + 4);
        if (POLL) {
            for (;;) {
                int a = vflag(ix0.x) & vflag(ix0.y) & vflag(ix0.z) & vflag(ix0.w)
                      & vflag(ix1.x) & vflag(ix1.y) & vflag(ix1.z) & vflag(ix1.w);
                if (a) break;
                __nanosleep(200);
            }
            __threadfence();
        }
        int4 v0 = __ldcg(reinterpret_cast<const int4*>(g_ftq + ((size_t)ix0.x << 10) + d0));
        int4 v1 = __ldcg(reinterpret_cast<const int4*>(g_ftq + ((size_t)ix0.y << 10) + d0));
        int4 v2 = __ldcg(reinterpret_cast<const int4*>(g_ftq + ((size_t)ix0.z << 10) + d0));
        int4 v3 = __ldcg(reinterpret_cast<const int4*>(g_ftq + ((size_t)ix0.w << 10) + d0));
        int4 v4 = __ldcg(reinterpret_cast<const int4*>(g_ftq + ((size_t)ix1.x << 10) + d0));
        int4 v5 = __ldcg(reinterpret_cast<const int4*>(g_ftq + ((size_t)ix1.y << 10) + d0));
        int4 v6 = __ldcg(reinterpret_cast<const int4*>(g_ftq + ((size_t)ix1.z << 10) + d0));
        int4 v7 = __ldcg(reinterpret_cast<const int4*>(g_ftq + ((size_t)ix1.w << 10) + d0));
        acc16(acc, v0); acc16(acc, v1); acc16(acc, v2); acc16(acc, v3);
        acc16(acc, v4); acc16(acc, v5); acc16(acc, v6); acc16(acc, v7);
    }
    for (; f < n; f++) {
        int r = feats[f];
        if (POLL) {
            while (!vflag(r)) __nanosleep(200);
            __threadfence();
        }
        const int4 v = __ldcg(reinterpret_cast<const int4*>(
            g_ftq + ((size_t)r << 10) + d0));
        acc16(acc, v);
    }
}

// ---- the single fused kernel ----------------------------------------------
__global__ __launch_bounds__(64, 20)
void fused_kernel(const int* __restrict__ wf,  const int* __restrict__ wo,
                  const int* __restrict__ bf,  const int* __restrict__ bo,
                  const int* __restrict__ stm, const int* __restrict__ bucket,
                  const float* __restrict__ ftw, const float* __restrict__ ftb,
                  const float* __restrict__ psq,
                  const float* __restrict__ f0w, const float* __restrict__ fc0b,
                  const float* __restrict__ f1w,
                  const float* __restrict__ fc1b, const float* __restrict__ fc2w,
                  const float* __restrict__ fc2b,
                  float* __restrict__ out, int nfeat_total, int nb)
{
    const int blk = blockIdx.x;
    const int tid = threadIdx.x;

    // ================= psqt zero-scan blocks =================
    if (blk < SCAN_BLOCKS) {
        int any = 0;
        const int base = blk * PSQ_PER_BLK;
        #pragma unroll 4
        for (int i = tid; i < PSQ_PER_BLK; i += 64) {
            float4 v = __ldcs(reinterpret_cast<const float4*>(psq) + base + i);
            any |= (v.x != 0.f) | (v.y != 0.f) | (v.z != 0.f) | (v.w != 0.f);
        }
        int r = __syncthreads_or(any);
        if (tid == 0)
            *((volatile int*)&g_sync.psq_part[blk]) = (r ? 3 : 2);  // done|nz
        return;
    }

    // ================= aux convert blocks (fc0/fc1/bias) =================
    if (blk < SCAN_BLOCKS + AUX_BLOCKS) {
        int a = blk - SCAN_BLOCKS;
        if (a < 128) {                          // fc0: 256 f4 per block
            int base = a * 256;
            #pragma unroll
            for (int j = 0; j < 4; j++) {
                int i = base + j * 64 + tid;
                float4 v = __ldcs(reinterpret_cast<const float4*>(f0w) + i);
                reinterpret_cast<char4*>(g_fc0q)[i] = q8x4(v);
            }
        } else if (a < 136) {                   // fc1: 256 f4 per block
            int base = (a - 128) * 256;
            #pragma unroll
            for (int j = 0; j < 4; j++) {
                int i = base + j * 64 + tid;
                float4 v = __ldcs(reinterpret_cast<const float4*>(f1w) + i);
                reinterpret_cast<char4*>(g_fc1q)[i] = q8x4(v);
            }
        } else {                                // bias: 512 packed words
            #pragma unroll
            for (int h = 0; h < 8; h++) {
                int w = tid * 8 + h;
                int b0 = (int)q16f(ftb[w * 2]);
                int b1 = (int)q16f(ftb[w * 2 + 1]);
                g_bq[w] = (unsigned)(b0 & 0xFFFF) | ((unsigned)b1 << 16);
            }
        }
        __threadfence();
        __syncthreads();
        if (tid == 0) { __threadfence(); atomicAdd(&g_sync.aux_done, 1); }
        return;
    }

    // ================= ft table convert blocks (4 rows each) =============
    if (blk < NN0) {
        const int k = blk - (SCAN_BLOCKS + AUX_BLOCKS);
        const size_t f4base = (size_t)k * 1024;        // 4 rows * 256 f4
        #pragma unroll 4
        for (int j = 0; j < 16; j++) {
            size_t i = f4base + j * 64 + tid;
            float4 v = __ldcs(reinterpret_cast<const float4*>(ftw) + i);
            reinterpret_cast<char4*>(g_ftq)[i] = q8x4(v);
        }
        __threadfence();
        __syncthreads();
        if (tid < 4)
            *((volatile int*)&g_sync.rowflag[k * 4 + tid]) = 1;
        if (tid == 0) { __threadfence(); atomicAdd(&g_sync.ft_done, 1); }
        return;
    }

    // ================= nnue blocks: one CTA per batch item ===============
    const int b    = blk - NN0;
    const int wid  = tid >> 5;
    const int lane = tid & 31;

    __shared__ __align__(16) int      s_wf[128], s_bf[128];
    __shared__ __align__(16) unsigned s_S[FT_OUT / 4];
    __shared__ __align__(16) unsigned s_O[FT_OUT / 4];
    __shared__ int   s_fc0p[32];
    __shared__ float s_o0[16];
    __shared__ float s_slab[32];
    __shared__ float s_psqt, s_scalar;
    __shared__ int   s_meta[6];   // ws,nw,bs,nbf,aux_ready(unused),ft_ready

    if (tid == 0) {
        int ws = wo[b];
        int we = (b + 1 < nb) ? wo[b + 1] : nfeat_total;
        int bs = bo[b];
        int be = (b + 1 < nb) ? bo[b + 1] : nfeat_total;
        s_meta[0] = ws; s_meta[1] = min(we - ws, 128);
        s_meta[2] = bs; s_meta[3] = min(be - bs, 128);
        // wait for aux tables (tiny; nearly always already done)
        while (*((volatile int*)&g_sync.aux_done) != AUX_BLOCKS) __nanosleep(128);
        s_meta[5] = (*((volatile int*)&g_sync.ft_done) == FT_CVT_BLOCKS);
    }
    __syncthreads();
    __threadfence();   // acquire for aux data
    const int ws  = s_meta[0], nw  = s_meta[1];
    const int bs  = s_meta[2], nbf = s_meta[3];
    const int ft_ready = s_meta[5];

    for (int i = tid; i < nw;  i += 64) s_wf[i] = wf[ws + i];
    for (int i = tid; i < nbf; i += 64) s_bf[i] = bf[bs + i];
    __syncthreads();

    const int st = stm[b];
    const int bk = bucket[b];
    const int d0 = tid * 16;

    #pragma unroll
    for (int side = 0; side < 2; side++) {
        const int* feats = side ? s_bf : s_wf;
        const int  n     = side ? nbf  : nw;
        unsigned acc[8] = {0,0,0,0,0,0,0,0};

        if (ft_ready) gather_side<false>(feats, n, d0, acc);
        else          gather_side<true >(feats, n, d0, acc);

        const uint4 bq0 = reinterpret_cast<const uint4*>(g_bq)[tid * 2];
        const uint4 bq1 = reinterpret_cast<const uint4*>(g_bq)[tid * 2 + 1];
        const unsigned biasp[8] = {bq0.x, bq0.y, bq0.z, bq0.w,
                                   bq1.x, bq1.y, bq1.z, bq1.w};

        unsigned pw[4];
        #pragma unroll
        for (int j = 0; j < 4; j++) {
            unsigned a01 = __vadd2(acc[2*j],     biasp[2*j]);
            unsigned a23 = __vadd2(acc[2*j + 1], biasp[2*j + 1]);
            a01 = __vmins2(__vmaxs2(a01, 0u), 0x007F007Fu);
            a23 = __vmins2(__vmaxs2(a23, 0u), 0x007F007Fu);
            pw[j] = __byte_perm(a01, a23, 0x6420);
        }
        unsigned* dst = (side ^ st) ? s_O : s_S;
        reinterpret_cast<uint4*>(dst)[tid] = make_uint4(pw[0], pw[1], pw[2], pw[3]);
    }
    __syncthreads();

    // pairwise products for my 16 dims, in registers
    int prod[8];
    {
        const unsigned* src = (tid < 32) ? s_S : s_O;
        const int tt = tid & 31;
        uint4 A = *reinterpret_cast<const uint4*>(src + 4 * tt);
        uint4 C = *reinterpret_cast<const uint4*>(src + 4 * tt + 128);
        mulbytes(A.x, C.x, prod[0], prod[1]);
        mulbytes(A.y, C.y, prod[2], prod[3]);
        mulbytes(A.z, C.z, prod[4], prod[5]);
        mulbytes(A.w, C.w, prod[6], prod[7]);
    }

    // fc0: 16 outputs via dp2a + REDUX
    {
        const signed char* wbase = g_fc0q + (bk << 14) + 16 * tid;
        #pragma unroll
        for (int o = 0; o < 16; o++) {
            int4 wv = *reinterpret_cast<const int4*>(wbase + (o << 10));
            int s = 0;
            s = __dp2a_lo(prod[0], wv.x, s);
            s = __dp2a_hi(prod[1], wv.x, s);
            s = __dp2a_lo(prod[2], wv.y, s);
            s = __dp2a_hi(prod[3], wv.y, s);
            s = __dp2a_lo(prod[4], wv.z, s);
            s = __dp2a_hi(prod[5], wv.z, s);
            s = __dp2a_lo(prod[6], wv.w, s);
            s = __dp2a_hi(prod[7], wv.w, s);
            int rsum = (int)__reduce_add_sync(0xffffffffu, (unsigned)s);
            if (lane == o) s_fc0p[wid * 16 + o] = rsum;
        }
    }
    __syncthreads();

    if (wid == 1) {
        // wait for psqt scan partials (cheap; usually already done)
        int part;
        for (;;) {
            part = (lane < 16) ? *((volatile int*)&g_sync.psq_part[lane]) : 2;
            if (__all_sync(0xffffffffu, part & 2)) break;
            __nanosleep(128);
        }
        if (__any_sync(0xffffffffu, part & 1)) {
            float ps = 0.f;
            for (int i = lane; i < nw;  i += 32)
                ps += q32f(psq[(size_t)s_wf[i] * 8 + bk]);
            for (int i = lane; i < nbf; i += 32)
                ps -= q32f(psq[(size_t)s_bf[i] * 8 + bk]);
            #pragma unroll
            for (int off = 16; off; off >>= 1)
                ps += __shfl_down_sync(0xffffffffu, ps, off);
            if (lane == 0) s_psqt = (st ? -ps : ps) * 0.5f;
        } else if (lane == 0) {
            s_psqt = 0.f;
        }
    } else {
        if (lane < 16) {
            int isum = s_fc0p[lane] + s_fc0p[16 + lane];
            s_o0[lane] = (float)isum * (1.f / 128.f) + q32f(fc0b[bk * 16 + lane]);
        }
        __syncwarp();

        float sl = 0.f;
        if (lane < 15) {
            float v = s_o0[lane];
            sl = clip127(v * v * (1.f / 524288.f));
        } else if (lane < 30) {
            float v = s_o0[lane - 15];
            sl = clip127(v * (1.f / 64.f));
        }
        s_slab[lane] = sl;
        __syncwarp();

        const signed char* w1 = g_fc1q + (bk * 32 + lane) * 32;
        uint4 wa = *reinterpret_cast<const uint4*>(w1);
        uint4 wb = *reinterpret_cast<const uint4*>(w1 + 16);
        const unsigned ww[8] = {wa.x, wa.y, wa.z, wa.w, wb.x, wb.y, wb.z, wb.w};
        float o1 = 0.f;
        #pragma unroll
        for (int q = 0; q < 8; q++) {
            o1 += s_slab[4*q + 0] * sb2f(ww[q], 0);
            o1 += s_slab[4*q + 1] * sb2f(ww[q], 1);
            o1 += s_slab[4*q + 2] * sb2f(ww[q], 2);
            o1 += s_slab[4*q + 3] * sb2f(ww[q], 3);
        }
        o1 += q32f(fc1b[bk * 32 + lane]);

        float a1 = clip127(o1 * (1.f / 64.f));
        float p  = a1 * q8f(fc2w[bk * 32 + lane]);
        #pragma unroll
        for (int off = 16; off; off >>= 1)
            p += __shfl_down_sync(0xffffffffu, p, off);
        if (lane == 0) {
            float scalar = p + q32f(fc2b[bk]);
            float skip   = s_o0[15] * (9600.f / 8128.f);
            s_scalar = scalar + skip;
        }
    }
    __syncthreads();

    if (tid == 0)
        out[b] = (s_psqt + s_scalar) * (1.f / 16.f);
}

extern "C" void kernel_launch(void* const* d_in, const int* in_sizes, int n_in,
                              void* d_out, int out_size)
{
    const int*   wf   = (const int*)d_in[0];
    const int*   wo   = (const int*)d_in[1];
    const int*   bfi  = (const int*)d_in[2];
    const int*   bo   = (const int*)d_in[3];
    const int*   stm  = (const int*)d_in[4];
    const int*   bkt  = (const int*)d_in[5];
    const float* ftw  = (const float*)d_in[6];
    const float* ftb  = (const float*)d_in[7];
    const float* psq  = (const float*)d_in[8];
    const float* f0w  = (const float*)d_in[9];
    const float* f0b  = (const float*)d_in[10];
    const float* f1w  = (const float*)d_in[11];
    const float* f1b  = (const float*)d_in[12];
    const float* f2w  = (const float*)d_in[13];
    const float* f2b  = (const float*)d_in[14];
    float* out = (float*)d_out;

    const int nb = in_sizes[4];
    const int nfeat_total = in_sizes[0];

    // Reset sync state (flags/counters) — capturable, no allocation.
    void* sync_ptr = nullptr;
    cudaGetSymbolAddress(&sync_ptr, g_sync);
    cudaMemsetAsync(sync_ptr, 0, sizeof(SyncT), 0);

    fused_kernel<<<NN0 + nb, 64>>>(wf, wo, bfi, bo, stm, bkt,
                                   ftw, ftb, psq, f0w, f0b, f1w, f1b, f2w, f2b,
                                   out, nfeat_total, nb);
}

// round 16
// speedup vs baseline: 1.1738x; 1.1738x over previous
#include <cuda_runtime.h>
#include <cstdint>

// ---------------------------------------------------------------------------
// GungnirHalfKA (NNUE) batched eval, GB300 sm_103a — Round 15
// R10 structure (best known) + wide-store cvt (8x f4/thread, 2x STG.128).
// ---------------------------------------------------------------------------

#define FT_IN   45056
#define FT_OUT  1024
#define NB_MAX  8

__device__ signed char g_ftq[(size_t)FT_IN * FT_OUT];   // 46 MB, int8-exact
__device__ signed char g_fc0q[NB_MAX * 16 * FT_OUT];    // 128 KB, int8-exact
__device__ signed char g_fc1q[NB_MAX * 32 * 32];        // 8 KB, int8-exact
__device__ unsigned    g_bq[FT_OUT / 2];                // ft bias, 2x i16 packed
__device__ int         g_psq_part[16];                  // psqt nonzero partials

__device__ __forceinline__ float q8f(float x) {
    return fminf(fmaxf(rintf(x), -128.f), 127.f);
}
__device__ __forceinline__ float q16f(float x) {
    return fminf(fmaxf(rintf(x), -32768.f), 32767.f);
}
__device__ __forceinline__ float q32f(float x) {
    return fminf(fmaxf(rintf(x), -2147483648.f), 2147483647.f);
}
__device__ __forceinline__ float clip127(float x) {
    return fminf(fmaxf(x, 0.f), 127.f);
}

// Widen 4 packed int8 -> 2x(2x int16) and accumulate.
__device__ __forceinline__ void acc4(unsigned* a, unsigned v) {
    unsigned lo, hi;
    asm("prmt.b32 %0, %1, 0, 0x9180;" : "=r"(lo) : "r"(v));
    asm("prmt.b32 %0, %1, 0, 0xB3A2;" : "=r"(hi) : "r"(v));
    a[0] = __vadd2(a[0], lo);
    a[1] = __vadd2(a[1], hi);
}
__device__ __forceinline__ void acc16(unsigned* acc, const int4& v) {
    acc4(acc + 0, (unsigned)v.x);
    acc4(acc + 2, (unsigned)v.y);
    acc4(acc + 4, (unsigned)v.z);
    acc4(acc + 6, (unsigned)v.w);
}

// 4 byte-pair products (u8*u8 <= 16129, fits positive s16) -> 2 packed words.
__device__ __forceinline__ void mulbytes(unsigned a, unsigned c,
                                         int& lo, int& hi) {
    lo = (int)(((a & 0xFFu) * (c & 0xFFu)) |
               ((((a >> 8) & 0xFFu) * ((c >> 8) & 0xFFu)) << 16));
    hi = (int)((((a >> 16) & 0xFFu) * ((c >> 16) & 0xFFu)) |
               (((a >> 24) * (c >> 24)) << 16));
}

// signed byte j of word w -> float
__device__ __forceinline__ float sb2f(unsigned w, int j) {
    return (float)((int)(w << (24 - 8 * j)) >> 24);
}

// float4 -> 4 packed quantized bytes
__device__ __forceinline__ unsigned q8pack(const float4& v) {
    unsigned u;
    u  = ((unsigned)(int)q8f(v.x)) & 0xFFu;
    u |= (((unsigned)(int)q8f(v.y)) & 0xFFu) << 8;
    u |= (((unsigned)(int)q8f(v.z)) & 0xFFu) << 16;
    u |= (((unsigned)(int)q8f(v.w)) & 0xFFu) << 24;
    return u;
}
__device__ __forceinline__ char4 q8x4(const float4& v) {
    char4 c;
    c.x = (signed char)q8f(v.x);
    c.y = (signed char)q8f(v.y);
    c.z = (signed char)q8f(v.z);
    c.w = (signed char)q8f(v.w);
    return c;
}

// Convert 8 consecutive float4s -> 32 bytes (2x STG.128).
__device__ __forceinline__ void cvt8(const float4* __restrict__ src,
                                     signed char* __restrict__ dstbase,
                                     size_t f4idx) {
    float4 v0 = __ldcs(src + f4idx + 0);
    float4 v1 = __ldcs(src + f4idx + 1);
    float4 v2 = __ldcs(src + f4idx + 2);
    float4 v3 = __ldcs(src + f4idx + 3);
    float4 v4 = __ldcs(src + f4idx + 4);
    float4 v5 = __ldcs(src + f4idx + 5);
    float4 v6 = __ldcs(src + f4idx + 6);
    float4 v7 = __ldcs(src + f4idx + 7);
    uint4 w0 = make_uint4(q8pack(v0), q8pack(v1), q8pack(v2), q8pack(v3));
    uint4 w1 = make_uint4(q8pack(v4), q8pack(v5), q8pack(v6), q8pack(v7));
    uint4* dst = reinterpret_cast<uint4*>(dstbase) + (f4idx >> 2);
    dst[0] = w0;
    dst[1] = w1;
}

// ---- cvt grid layout ------------------------------------------------------
// [0,16)            psqt zero-scan partials
// [16, +FT_CVT)     ft_weight -> int8 (2048 f4 per block, 8 per thread)
// [.., +FC0_CVT)    fc0_w -> int8
// [.., +FC1_CVT)    fc1_w -> int8
// last block        ft_bias -> packed i16
#define SCAN_BLOCKS 16
#define PSQ_F4      (FT_IN * 8 / 4)            /* 90112 */
#define PSQ_PER_BLK (PSQ_F4 / SCAN_BLOCKS)     /* 5632  */
#define FT_F4_TOTAL ((size_t)FT_IN * FT_OUT / 4)
#define FT_CVT      (FT_IN / 8)                /* 5632 blocks, 2048 f4 each */
#define FC0_F4      (NB_MAX * 16 * FT_OUT / 4) /* 32768 */
#define FC0_CVT     (FC0_F4 / 2048)            /* 16 */
#define FC1_F4      (NB_MAX * 32 * 32 / 4)     /* 2048 */
#define FC1_CVT     1
#define CVT_BLOCKS  (SCAN_BLOCKS + FT_CVT + FC0_CVT + FC1_CVT + 1)

__global__ void cvt_kernel(const float* __restrict__ ftw,
                           const float* __restrict__ f0w,
                           const float* __restrict__ f1w,
                           const float* __restrict__ ftb,
                           const float* __restrict__ psq) {
    const int blk = blockIdx.x;
    const int tid = threadIdx.x;

    if (blk < SCAN_BLOCKS) {
        int any = 0;
        const int base = blk * PSQ_PER_BLK;
        #pragma unroll 4
        for (int i = tid; i < PSQ_PER_BLK; i += 256) {
            float4 v = __ldcs(reinterpret_cast<const float4*>(psq) + base + i);
            any |= (v.x != 0.f) | (v.y != 0.f) | (v.z != 0.f) | (v.w != 0.f);
        }
        int r = __syncthreads_or(any);
        if (tid == 0) g_psq_part[blk] = r;
        return;
    }
    int k = blk - SCAN_BLOCKS;
    if (k < FT_CVT) {
        cvt8(reinterpret_cast<const float4*>(ftw), g_ftq,
             (size_t)k * 2048 + (size_t)tid * 8);
        return;
    }
    k -= FT_CVT;
    if (k < FC0_CVT) {
        cvt8(reinterpret_cast<const float4*>(f0w), g_fc0q,
             (size_t)k * 2048 + (size_t)tid * 8);
        return;
    }
    k -= FC0_CVT;
    if (k < FC1_CVT) {
        cvt8(reinterpret_cast<const float4*>(f1w), g_fc1q,
             (size_t)tid * 8);
        return;
    }
    // bias block
    #pragma unroll
    for (int h = 0; h < 2; h++) {
        int w = tid * 2 + h;
        int b0 = (int)q16f(ftb[w * 2]);
        int b1 = (int)q16f(ftb[w * 2 + 1]);
        g_bq[w] = (unsigned)(b0 & 0xFFFF) | ((unsigned)b1 << 16);
    }
}

// ---- main fused kernel: one 64-thread CTA per batch item ------------------
__global__ __launch_bounds__(64, 20)
void nnue_kernel(const int* __restrict__ wf,  const int* __restrict__ wo,
                 const int* __restrict__ bf,  const int* __restrict__ bo,
                 const int* __restrict__ stm, const int* __restrict__ bucket,
                 const float* __restrict__ psq,
                 const float* __restrict__ fc0b,
                 const float* __restrict__ fc1b, const float* __restrict__ fc2w,
                 const float* __restrict__ fc2b,
                 float* __restrict__ out, int nfeat_total, int nb)
{
    const int b    = blockIdx.x;
    const int tid  = threadIdx.x;
    const int wid  = tid >> 5;
    const int lane = tid & 31;

    __shared__ __align__(16) int      s_wf[128], s_bf[128];
    __shared__ __align__(16) unsigned s_S[FT_OUT / 4];   // clipped acc_stm u8
    __shared__ __align__(16) unsigned s_O[FT_OUT / 4];   // clipped acc_opp u8
    __shared__ int   s_fc0p[32];
    __shared__ float s_o0[16];
    __shared__ float s_slab[32];
    __shared__ float s_psqt, s_scalar;
    __shared__ int   s_meta[4];

    if (tid == 0) {
        int ws = wo[b];
        int we = (b + 1 < nb) ? wo[b + 1] : nfeat_total;
        int bs = bo[b];
        int be = (b + 1 < nb) ? bo[b + 1] : nfeat_total;
        s_meta[0] = ws; s_meta[1] = min(we - ws, 128);
        s_meta[2] = bs; s_meta[3] = min(be - bs, 128);
    }
    __syncthreads();
    const int ws  = s_meta[0], nw  = s_meta[1];
    const int bs  = s_meta[2], nbf = s_meta[3];

    for (int i = tid; i < nw;  i += 64) s_wf[i] = wf[ws + i];
    for (int i = tid; i < nbf; i += 64) s_bf[i] = bf[bs + i];
    __syncthreads();

    const int st = stm[b];
    const int bk = bucket[b];
    const int d0 = tid * 16;

    // ---- gather both sides; clip+pack to u8, single STS.128 per side -----
    #pragma unroll
    for (int side = 0; side < 2; side++) {
        const int* feats = side ? s_bf : s_wf;
        const int  n     = side ? nbf  : nw;
        unsigned acc[8] = {0,0,0,0,0,0,0,0};

        int f = 0;
        for (; f + 8 <= n; f += 8) {
            int4 ix0 = *reinterpret_cast<const int4*>(feats + f);
            int4 ix1 = *reinterpret_cast<const int4*>(feats + f + 4);
            int4 v0 = __ldcg(reinterpret_cast<const int4*>(g_ftq + ((size_t)ix0.x << 10) + d0));
            int4 v1 = __ldcg(reinterpret_cast<const int4*>(g_ftq + ((size_t)ix0.y << 10) + d0));
            int4 v2 = __ldcg(reinterpret_cast<const int4*>(g_ftq + ((size_t)ix0.z << 10) + d0));
            int4 v3 = __ldcg(reinterpret_cast<const int4*>(g_ftq + ((size_t)ix0.w << 10) + d0));
            int4 v4 = __ldcg(reinterpret_cast<const int4*>(g_ftq + ((size_t)ix1.x << 10) + d0));
            int4 v5 = __ldcg(reinterpret_cast<const int4*>(g_ftq + ((size_t)ix1.y << 10) + d0));
            int4 v6 = __ldcg(reinterpret_cast<const int4*>(g_ftq + ((size_t)ix1.z << 10) + d0));
            int4 v7 = __ldcg(reinterpret_cast<const int4*>(g_ftq + ((size_t)ix1.w << 10) + d0));
            acc16(acc, v0); acc16(acc, v1); acc16(acc, v2); acc16(acc, v3);
            acc16(acc, v4); acc16(acc, v5); acc16(acc, v6); acc16(acc, v7);
        }
        for (; f < n; f++) {
            const int4 v = __ldcg(reinterpret_cast<const int4*>(
                g_ftq + ((size_t)feats[f] << 10) + d0));
            acc16(acc, v);
        }

        const uint4 bq0 = reinterpret_cast<const uint4*>(g_bq)[tid * 2];
        const uint4 bq1 = reinterpret_cast<const uint4*>(g_bq)[tid * 2 + 1];
        const unsigned biasp[8] = {bq0.x, bq0.y, bq0.z, bq0.w,
                                   bq1.x, bq1.y, bq1.z, bq1.w};

        unsigned pw[4];
        #pragma unroll
        for (int j = 0; j < 4; j++) {
            unsigned a01 = __vadd2(acc[2*j],     biasp[2*j]);
            unsigned a23 = __vadd2(acc[2*j + 1], biasp[2*j + 1]);
            a01 = __vmins2(__vmaxs2(a01, 0u), 0x007F007Fu);
            a23 = __vmins2(__vmaxs2(a23, 0u), 0x007F007Fu);
            pw[j] = __byte_perm(a01, a23, 0x6420);
        }
        unsigned* dst = (side ^ st) ? s_O : s_S;
        reinterpret_cast<uint4*>(dst)[tid] = make_uint4(pw[0], pw[1], pw[2], pw[3]);
    }
    __syncthreads();

    // ---- pairwise products for MY 16 dims, kept in registers -------------
    int prod[8];
    {
        const unsigned* src = (tid < 32) ? s_S : s_O;
        const int tt = tid & 31;
        uint4 A = *reinterpret_cast<const uint4*>(src + 4 * tt);
        uint4 C = *reinterpret_cast<const uint4*>(src + 4 * tt + 128);
        mulbytes(A.x, C.x, prod[0], prod[1]);
        mulbytes(A.y, C.y, prod[2], prod[3]);
        mulbytes(A.z, C.z, prod[4], prod[5]);
        mulbytes(A.w, C.w, prod[6], prod[7]);
    }

    // ---- fc0: all threads, all 16 outputs over own dims; REDUX per warp --
    {
        const signed char* wbase = g_fc0q + (bk << 14) + 16 * tid;
        #pragma unroll
        for (int o = 0; o < 16; o++) {
            int4 wv = *reinterpret_cast<const int4*>(wbase + (o << 10));
            int s = 0;
            s = __dp2a_lo(prod[0], wv.x, s);
            s = __dp2a_hi(prod[1], wv.x, s);
            s = __dp2a_lo(prod[2], wv.y, s);
            s = __dp2a_hi(prod[3], wv.y, s);
            s = __dp2a_lo(prod[4], wv.z, s);
            s = __dp2a_hi(prod[5], wv.z, s);
            s = __dp2a_lo(prod[6], wv.w, s);
            s = __dp2a_hi(prod[7], wv.w, s);
            int rsum = (int)__reduce_add_sync(0xffffffffu, (unsigned)s);
            if (lane == o) s_fc0p[wid * 16 + o] = rsum;
        }
    }
    __syncthreads();

    // ---- warp 1: psqt (only if table nonzero); warp 0: tail MLP ----------
    if (wid == 1) {
        int nzp = (lane < 16) ? g_psq_part[lane] : 0;
        if (__any_sync(0xffffffffu, nzp)) {
            float ps = 0.f;
            for (int i = lane; i < nw;  i += 32)
                ps += q32f(psq[(size_t)s_wf[i] * 8 + bk]);
            for (int i = lane; i < nbf; i += 32)
                ps -= q32f(psq[(size_t)s_bf[i] * 8 + bk]);
            #pragma unroll
            for (int off = 16; off; off >>= 1)
                ps += __shfl_down_sync(0xffffffffu, ps, off);
            if (lane == 0) s_psqt = (st ? -ps : ps) * 0.5f;
        } else if (lane == 0) {
            s_psqt = 0.f;
        }
    } else {
        if (lane < 16) {
            int isum = s_fc0p[lane] + s_fc0p[16 + lane];
            s_o0[lane] = (float)isum * (1.f / 128.f) + q32f(fc0b[bk * 16 + lane]);
        }
        __syncwarp();

        float sl = 0.f;
        if (lane < 15) {
            float v = s_o0[lane];
            sl = clip127(v * v * (1.f / 524288.f));       // 1<<19
        } else if (lane < 30) {
            float v = s_o0[lane - 15];
            sl = clip127(v * (1.f / 64.f));
        }
        s_slab[lane] = sl;
        __syncwarp();

        const signed char* w1 = g_fc1q + (bk * 32 + lane) * 32;
        uint4 wa = *reinterpret_cast<const uint4*>(w1);
        uint4 wb = *reinterpret_cast<const uint4*>(w1 + 16);
        const unsigned ww[8] = {wa.x, wa.y, wa.z, wa.w, wb.x, wb.y, wb.z, wb.w};
        float o1 = 0.f;
        #pragma unroll
        for (int q = 0; q < 8; q++) {
            o1 += s_slab[4*q + 0] * sb2f(ww[q], 0);
            o1 += s_slab[4*q + 1] * sb2f(ww[q], 1);
            o1 += s_slab[4*q + 2] * sb2f(ww[q], 2);
            o1 += s_slab[4*q + 3] * sb2f(ww[q], 3);
        }
        o1 += q32f(fc1b[bk * 32 + lane]);

        float a1 = clip127(o1 * (1.f / 64.f));
        float p  = a1 * q8f(fc2w[bk * 32 + lane]);
        #pragma unroll
        for (int off = 16; off; off >>= 1)
            p += __shfl_down_sync(0xffffffffu, p, off);
        if (lane == 0) {
            float scalar = p + q32f(fc2b[bk]);
            float skip   = s_o0[15] * (9600.f / 8128.f);
            s_scalar = scalar + skip;
        }
    }
    __syncthreads();

    if (tid == 0)
        out[b] = (s_psqt + s_scalar) * (1.f / 16.f);
}

extern "C" void kernel_launch(void* const* d_in, const int* in_sizes, int n_in,
                              void* d_out, int out_size)
{
    const int*   wf   = (const int*)d_in[0];
    const int*   wo   = (const int*)d_in[1];
    const int*   bfi  = (const int*)d_in[2];
    const int*   bo   = (const int*)d_in[3];
    const int*   stm  = (const int*)d_in[4];
    const int*   bkt  = (const int*)d_in[5];
    const float* ftw  = (const float*)d_in[6];
    const float* ftb  = (const float*)d_in[7];
    const float* psq  = (const float*)d_in[8];
    const float* f0w  = (const float*)d_in[9];
    const float* f0b  = (const float*)d_in[10];
    const float* f1w  = (const float*)d_in[11];
    const float* f1b  = (const float*)d_in[12];
    const float* f2w  = (const float*)d_in[13];
    const float* f2b  = (const float*)d_in[14];
    float* out = (float*)d_out;

    const int nb = in_sizes[4];
    const int nfeat_total = in_sizes[0];

    cvt_kernel<<<CVT_BLOCKS, 256>>>(ftw, f0w, f1w, ftb, psq);

    nnue_kernel<<<nb, 64>>>(wf, wo, bfi, bo, stm, bkt,
                            psq, f0b, f1b, f2w, f2b,
                            out, nfeat_total, nb);
}

// round 17
// speedup vs baseline: 1.4004x; 1.1931x over previous
#include <cuda_runtime.h>
#include <cstdint>

// ---------------------------------------------------------------------------
// GungnirHalfKA (NNUE) batched eval, GB300 sm_103a — Round 16
// R10 structure (best known). cvt: coalesced layout, 8 float4/thread (MLP 8).
// ---------------------------------------------------------------------------

#define FT_IN   45056
#define FT_OUT  1024
#define NB_MAX  8

__device__ signed char g_ftq[(size_t)FT_IN * FT_OUT];   // 46 MB, int8-exact
__device__ signed char g_fc0q[NB_MAX * 16 * FT_OUT];    // 128 KB, int8-exact
__device__ signed char g_fc1q[NB_MAX * 32 * 32];        // 8 KB, int8-exact
__device__ unsigned    g_bq[FT_OUT / 2];                // ft bias, 2x i16 packed
__device__ int         g_psq_part[16];                  // psqt nonzero partials

__device__ __forceinline__ float q8f(float x) {
    return fminf(fmaxf(rintf(x), -128.f), 127.f);
}
__device__ __forceinline__ float q16f(float x) {
    return fminf(fmaxf(rintf(x), -32768.f), 32767.f);
}
__device__ __forceinline__ float q32f(float x) {
    return fminf(fmaxf(rintf(x), -2147483648.f), 2147483647.f);
}
__device__ __forceinline__ float clip127(float x) {
    return fminf(fmaxf(x, 0.f), 127.f);
}

// Widen 4 packed int8 -> 2x(2x int16) and accumulate.
__device__ __forceinline__ void acc4(unsigned* a, unsigned v) {
    unsigned lo, hi;
    asm("prmt.b32 %0, %1, 0, 0x9180;" : "=r"(lo) : "r"(v));
    asm("prmt.b32 %0, %1, 0, 0xB3A2;" : "=r"(hi) : "r"(v));
    a[0] = __vadd2(a[0], lo);
    a[1] = __vadd2(a[1], hi);
}
__device__ __forceinline__ void acc16(unsigned* acc, const int4& v) {
    acc4(acc + 0, (unsigned)v.x);
    acc4(acc + 2, (unsigned)v.y);
    acc4(acc + 4, (unsigned)v.z);
    acc4(acc + 6, (unsigned)v.w);
}

// 4 byte-pair products (u8*u8 <= 16129, fits positive s16) -> 2 packed words.
__device__ __forceinline__ void mulbytes(unsigned a, unsigned c,
                                         int& lo, int& hi) {
    lo = (int)(((a & 0xFFu) * (c & 0xFFu)) |
               ((((a >> 8) & 0xFFu) * ((c >> 8) & 0xFFu)) << 16));
    hi = (int)((((a >> 16) & 0xFFu) * ((c >> 16) & 0xFFu)) |
               (((a >> 24) * (c >> 24)) << 16));
}

// signed byte j of word w -> float
__device__ __forceinline__ float sb2f(unsigned w, int j) {
    return (float)((int)(w << (24 - 8 * j)) >> 24);
}
__device__ __forceinline__ char4 q8x4(const float4& v) {
    char4 c;
    c.x = (signed char)q8f(v.x);
    c.y = (signed char)q8f(v.y);
    c.z = (signed char)q8f(v.z);
    c.w = (signed char)q8f(v.w);
    return c;
}

// ---- cvt grid layout ------------------------------------------------------
// [0,16)            psqt zero-scan partials
// [16, +FT_CVT)     ft_weight -> int8: 2048 f4 per block, COALESCED
//                   (i = base + j*256 + tid), 8 f4 per thread
// [.., +FC0_CVT)    fc0_w -> int8 (coalesced, 4/thread)
// [.., +FC1_CVT)    fc1_w -> int8
// last block        ft_bias -> packed i16
#define SCAN_BLOCKS 16
#define PSQ_F4      (FT_IN * 8 / 4)            /* 90112 */
#define PSQ_PER_BLK (PSQ_F4 / SCAN_BLOCKS)     /* 5632  */
#define FT_CVT      (FT_IN / 8)                /* 5632 blocks x 2048 f4 */
#define FC0_F4      (NB_MAX * 16 * FT_OUT / 4) /* 32768 */
#define FC0_CVT     (FC0_F4 / 1024)            /* 32 */
#define FC1_F4      (NB_MAX * 32 * 32 / 4)     /* 2048 */
#define FC1_CVT     (FC1_F4 / 1024)            /* 2 */
#define CVT_BLOCKS  (SCAN_BLOCKS + FT_CVT + FC0_CVT + FC1_CVT + 1)

__global__ void cvt_kernel(const float* __restrict__ ftw,
                           const float* __restrict__ f0w,
                           const float* __restrict__ f1w,
                           const float* __restrict__ ftb,
                           const float* __restrict__ psq) {
    const int blk = blockIdx.x;
    const int tid = threadIdx.x;

    if (blk < SCAN_BLOCKS) {
        int any = 0;
        const int base = blk * PSQ_PER_BLK;
        #pragma unroll 4
        for (int i = tid; i < PSQ_PER_BLK; i += 256) {
            float4 v = __ldcs(reinterpret_cast<const float4*>(psq) + base + i);
            any |= (v.x != 0.f) | (v.y != 0.f) | (v.z != 0.f) | (v.w != 0.f);
        }
        int r = __syncthreads_or(any);
        if (tid == 0) g_psq_part[blk] = r;
        return;
    }
    int k = blk - SCAN_BLOCKS;
    if (k < FT_CVT) {
        // 2048 float4 per block, coalesced: 8 independent loads in flight.
        const size_t base = (size_t)k * 2048;
        float4 v[8];
        #pragma unroll
        for (int j = 0; j < 8; j++)
            v[j] = __ldcs(reinterpret_cast<const float4*>(ftw) + base + j * 256 + tid);
        #pragma unroll
        for (int j = 0; j < 8; j++)
            reinterpret_cast<char4*>(g_ftq)[base + j * 256 + tid] = q8x4(v[j]);
        return;
    }
    k -= FT_CVT;
    if (k < FC0_CVT) {
        const int base = k * 1024;
        #pragma unroll
        for (int j = 0; j < 4; j++) {
            int i = base + j * 256 + tid;
            float4 v = __ldcs(reinterpret_cast<const float4*>(f0w) + i);
            reinterpret_cast<char4*>(g_fc0q)[i] = q8x4(v);
        }
        return;
    }
    k -= FC0_CVT;
    if (k < FC1_CVT) {
        const int base = k * 1024;
        #pragma unroll
        for (int j = 0; j < 4; j++) {
            int i = base + j * 256 + tid;
            float4 v = __ldcs(reinterpret_cast<const float4*>(f1w) + i);
            reinterpret_cast<char4*>(g_fc1q)[i] = q8x4(v);
        }
        return;
    }
    // bias block
    #pragma unroll
    for (int h = 0; h < 2; h++) {
        int w = tid * 2 + h;
        int b0 = (int)q16f(ftb[w * 2]);
        int b1 = (int)q16f(ftb[w * 2 + 1]);
        g_bq[w] = (unsigned)(b0 & 0xFFFF) | ((unsigned)b1 << 16);
    }
}

// ---- main fused kernel: one 64-thread CTA per batch item ------------------
__global__ __launch_bounds__(64, 20)
void nnue_kernel(const int* __restrict__ wf,  const int* __restrict__ wo,
                 const int* __restrict__ bf,  const int* __restrict__ bo,
                 const int* __restrict__ stm, const int* __restrict__ bucket,
                 const float* __restrict__ psq,
                 const float* __restrict__ fc0b,
                 const float* __restrict__ fc1b, const float* __restrict__ fc2w,
                 const float* __restrict__ fc2b,
                 float* __restrict__ out, int nfeat_total, int nb)
{
    const int b    = blockIdx.x;
    const int tid  = threadIdx.x;
    const int wid  = tid >> 5;
    const int lane = tid & 31;

    __shared__ __align__(16) int      s_wf[128], s_bf[128];
    __shared__ __align__(16) unsigned s_S[FT_OUT / 4];   // clipped acc_stm u8
    __shared__ __align__(16) unsigned s_O[FT_OUT / 4];   // clipped acc_opp u8
    __shared__ int   s_fc0p[32];
    __shared__ float s_o0[16];
    __shared__ float s_slab[32];
    __shared__ float s_psqt, s_scalar;
    __shared__ int   s_meta[4];

    if (tid == 0) {
        int ws = wo[b];
        int we = (b + 1 < nb) ? wo[b + 1] : nfeat_total;
        int bs = bo[b];
        int be = (b + 1 < nb) ? bo[b + 1] : nfeat_total;
        s_meta[0] = ws; s_meta[1] = min(we - ws, 128);
        s_meta[2] = bs; s_meta[3] = min(be - bs, 128);
    }
    __syncthreads();
    const int ws  = s_meta[0], nw  = s_meta[1];
    const int bs  = s_meta[2], nbf = s_meta[3];

    for (int i = tid; i < nw;  i += 64) s_wf[i] = wf[ws + i];
    for (int i = tid; i < nbf; i += 64) s_bf[i] = bf[bs + i];
    __syncthreads();

    const int st = stm[b];
    const int bk = bucket[b];
    const int d0 = tid * 16;

    // ---- gather both sides; clip+pack to u8, single STS.128 per side -----
    #pragma unroll
    for (int side = 0; side < 2; side++) {
        const int* feats = side ? s_bf : s_wf;
        const int  n     = side ? nbf  : nw;
        unsigned acc[8] = {0,0,0,0,0,0,0,0};

        int f = 0;
        for (; f + 8 <= n; f += 8) {
            int4 ix0 = *reinterpret_cast<const int4*>(feats + f);
            int4 ix1 = *reinterpret_cast<const int4*>(feats + f + 4);
            int4 v0 = __ldcg(reinterpret_cast<const int4*>(g_ftq + ((size_t)ix0.x << 10) + d0));
            int4 v1 = __ldcg(reinterpret_cast<const int4*>(g_ftq + ((size_t)ix0.y << 10) + d0));
            int4 v2 = __ldcg(reinterpret_cast<const int4*>(g_ftq + ((size_t)ix0.z << 10) + d0));
            int4 v3 = __ldcg(reinterpret_cast<const int4*>(g_ftq + ((size_t)ix0.w << 10) + d0));
            int4 v4 = __ldcg(reinterpret_cast<const int4*>(g_ftq + ((size_t)ix1.x << 10) + d0));
            int4 v5 = __ldcg(reinterpret_cast<const int4*>(g_ftq + ((size_t)ix1.y << 10) + d0));
            int4 v6 = __ldcg(reinterpret_cast<const int4*>(g_ftq + ((size_t)ix1.z << 10) + d0));
            int4 v7 = __ldcg(reinterpret_cast<const int4*>(g_ftq + ((size_t)ix1.w << 10) + d0));
            acc16(acc, v0); acc16(acc, v1); acc16(acc, v2); acc16(acc, v3);
            acc16(acc, v4); acc16(acc, v5); acc16(acc, v6); acc16(acc, v7);
        }
        for (; f < n; f++) {
            const int4 v = __ldcg(reinterpret_cast<const int4*>(
                g_ftq + ((size_t)feats[f] << 10) + d0));
            acc16(acc, v);
        }

        const uint4 bq0 = reinterpret_cast<const uint4*>(g_bq)[tid * 2];
        const uint4 bq1 = reinterpret_cast<const uint4*>(g_bq)[tid * 2 + 1];
        const unsigned biasp[8] = {bq0.x, bq0.y, bq0.z, bq0.w,
                                   bq1.x, bq1.y, bq1.z, bq1.w};

        unsigned pw[4];
        #pragma unroll
        for (int j = 0; j < 4; j++) {
            unsigned a01 = __vadd2(acc[2*j],     biasp[2*j]);
            unsigned a23 = __vadd2(acc[2*j + 1], biasp[2*j + 1]);
            a01 = __vmins2(__vmaxs2(a01, 0u), 0x007F007Fu);
            a23 = __vmins2(__vmaxs2(a23, 0u), 0x007F007Fu);
            pw[j] = __byte_perm(a01, a23, 0x6420);
        }
        unsigned* dst = (side ^ st) ? s_O : s_S;
        reinterpret_cast<uint4*>(dst)[tid] = make_uint4(pw[0], pw[1], pw[2], pw[3]);
    }
    __syncthreads();

    // ---- pairwise products for MY 16 dims, kept in registers -------------
    int prod[8];
    {
        const unsigned* src = (tid < 32) ? s_S : s_O;
        const int tt = tid & 31;
        uint4 A = *reinterpret_cast<const uint4*>(src + 4 * tt);
        uint4 C = *reinterpret_cast<const uint4*>(src + 4 * tt + 128);
        mulbytes(A.x, C.x, prod[0], prod[1]);
        mulbytes(A.y, C.y, prod[2], prod[3]);
        mulbytes(A.z, C.z, prod[4], prod[5]);
        mulbytes(A.w, C.w, prod[6], prod[7]);
    }

    // ---- fc0: all threads, all 16 outputs over own dims; REDUX per warp --
    {
        const signed char* wbase = g_fc0q + (bk << 14) + 16 * tid;
        #pragma unroll
        for (int o = 0; o < 16; o++) {
            int4 wv = *reinterpret_cast<const int4*>(wbase + (o << 10));
            int s = 0;
            s = __dp2a_lo(prod[0], wv.x, s);
            s = __dp2a_hi(prod[1], wv.x, s);
            s = __dp2a_lo(prod[2], wv.y, s);
            s = __dp2a_hi(prod[3], wv.y, s);
            s = __dp2a_lo(prod[4], wv.z, s);
            s = __dp2a_hi(prod[5], wv.z, s);
            s = __dp2a_lo(prod[6], wv.w, s);
            s = __dp2a_hi(prod[7], wv.w, s);
            int rsum = (int)__reduce_add_sync(0xffffffffu, (unsigned)s);
            if (lane == o) s_fc0p[wid * 16 + o] = rsum;
        }
    }
    __syncthreads();

    // ---- warp 1: psqt (only if table nonzero); warp 0: tail MLP ----------
    if (wid == 1) {
        int nzp = (lane < 16) ? g_psq_part[lane] : 0;
        if (__any_sync(0xffffffffu, nzp)) {
            float ps = 0.f;
            for (int i = lane; i < nw;  i += 32)
                ps += q32f(psq[(size_t)s_wf[i] * 8 + bk]);
            for (int i = lane; i < nbf; i += 32)
                ps -= q32f(psq[(size_t)s_bf[i] * 8 + bk]);
            #pragma unroll
            for (int off = 16; off; off >>= 1)
                ps += __shfl_down_sync(0xffffffffu, ps, off);
            if (lane == 0) s_psqt = (st ? -ps : ps) * 0.5f;
        } else if (lane == 0) {
            s_psqt = 0.f;
        }
    } else {
        if (lane < 16) {
            int isum = s_fc0p[lane] + s_fc0p[16 + lane];
            s_o0[lane] = (float)isum * (1.f / 128.f) + q32f(fc0b[bk * 16 + lane]);
        }
        __syncwarp();

        float sl = 0.f;
        if (lane < 15) {
            float v = s_o0[lane];
            sl = clip127(v * v * (1.f / 524288.f));       // 1<<19
        } else if (lane < 30) {
            float v = s_o0[lane - 15];
            sl = clip127(v * (1.f / 64.f));
        }
        s_slab[lane] = sl;
        __syncwarp();

        const signed char* w1 = g_fc1q + (bk * 32 + lane) * 32;
        uint4 wa = *reinterpret_cast<const uint4*>(w1);
        uint4 wb = *reinterpret_cast<const uint4*>(w1 + 16);
        const unsigned ww[8] = {wa.x, wa.y, wa.z, wa.w, wb.x, wb.y, wb.z, wb.w};
        float o1 = 0.f;
        #pragma unroll
        for (int q = 0; q < 8; q++) {
            o1 += s_slab[4*q + 0] * sb2f(ww[q], 0);
            o1 += s_slab[4*q + 1] * sb2f(ww[q], 1);
            o1 += s_slab[4*q + 2] * sb2f(ww[q], 2);
            o1 += s_slab[4*q + 3] * sb2f(ww[q], 3);
        }
        o1 += q32f(fc1b[bk * 32 + lane]);

        float a1 = clip127(o1 * (1.f / 64.f));
        float p  = a1 * q8f(fc2w[bk * 32 + lane]);
        #pragma unroll
        for (int off = 16; off; off >>= 1)
            p += __shfl_down_sync(0xffffffffu, p, off);
        if (lane == 0) {
            float scalar = p + q32f(fc2b[bk]);
            float skip   = s_o0[15] * (9600.f / 8128.f);
            s_scalar = scalar + skip;
        }
    }
    __syncthreads();

    if (tid == 0)
        out[b] = (s_psqt + s_scalar) * (1.f / 16.f);
}

extern "C" void kernel_launch(void* const* d_in, const int* in_sizes, int n_in,
                              void* d_out, int out_size)
{
    const int*   wf   = (const int*)d_in[0];
    const int*   wo   = (const int*)d_in[1];
    const int*   bfi  = (const int*)d_in[2];
    const int*   bo   = (const int*)d_in[3];
    const int*   stm  = (const int*)d_in[4];
    const int*   bkt  = (const int*)d_in[5];
    const float* ftw  = (const float*)d_in[6];
    const float* ftb  = (const float*)d_in[7];
    const float* psq  = (const float*)d_in[8];
    const float* f0w  = (const float*)d_in[9];
    const float* f0b  = (const float*)d_in[10];
    const float* f1w  = (const float*)d_in[11];
    const float* f1b  = (const float*)d_in[12];
    const float* f2w  = (const float*)d_in[13];
    const float* f2b  = (const float*)d_in[14];
    float* out = (float*)d_out;

    const int nb = in_sizes[4];
    const int nfeat_total = in_sizes[0];

    cvt_kernel<<<CVT_BLOCKS, 256>>>(ftw, f0w, f1w, ftb, psq);

    nnue_kernel<<<nb, 64>>>(wf, wo, bfi, bo, stm, bkt,
                            psq, f0b, f1b, f2w, f2b,
                            out, nfeat_total, nb);
}